// round 15
// baseline (speedup 1.0000x reference)
#include <cuda_runtime.h>
#include <math.h>

#define PS      32
#define NPIX    1024
#define NBINS   36
#define THREADS 128

__device__ __forceinline__ float sqrt_approx(float v) {
    float r;
    asm("sqrt.approx.f32 %0, %1;" : "=f"(r) : "f"(v));
    return r;
}

__global__ __launch_bounds__(THREADS, 8)
void orientation_kernel(const float* __restrict__ x,
                        const float* __restrict__ gxw,
                        const float* __restrict__ gyw,
                        const float* __restrict__ smw,
                        const float* __restrict__ gk,
                        float* __restrict__ out)
{
    // Transposed histogram: hist[bin*THREADS + tid].
    // Scatter bank = tid mod 32 = lane -> conflict-free for ANY bin pattern.
    __shared__ float hist[NBINS * THREADS];
    __shared__ float hred[NBINS];
    __shared__ float smarr[NBINS];

    const int tid  = threadIdx.x;
    const int lane = tid & 31;
    const int wrp  = tid >> 5;
    const int q    = lane & 7;          // col-quad: cols 4q..4q+3
    const int rg   = lane >> 3;         // rowgroup within warp
    const int blk  = blockIdx.x;

    const float TWO_PI_F = __int_as_float(0x40C90FDB);   // RN(2*pi)
    const float INV_2PI  = __int_as_float(0x3E22F983);   // RN(1/(2*pi))
    const float PI_F     = 3.141592653589793f;

    // ---- zero histogram: 36*128 floats = 1152 float4 = exactly 9 per thread ----
    {
        float4 z = make_float4(0.f, 0.f, 0.f, 0.f);
        float4* h4 = (float4*)hist;
        #pragma unroll
        for (int i = 0; i < 9; i++)
            h4[tid + i * THREADS] = z;
    }

    // gx_w = [0.5, 0, -0.5], gy_w likewise: gw1*c contributes +0 exactly and
    // gw2 = -gw0, so ref chain RN(gw0*a + 0) + RN(gw2*b) == RN(gw0*a - gw0*b)
    // == gw0 * RN(a-b) (gw0 = 2^-1; scaling by a power of two commutes with RN).
    const float gw0 = gxw[0];
    const float hw0 = gyw[0];

    // ---- vectorized loads: thread owns rows rb,rb+1 x cols 4q..4q+3 ----
    const int g  = wrp * 4 + rg;        // global rowgroup 0..15
    const int rb = 2 * g;               // base row (even)
    const int rm = (rb - 1 < 0) ? 0 : rb - 1;
    const int rp = (rb + 2 > PS - 1) ? PS - 1 : rb + 2;

    const float4* xp = (const float4*)(x + (size_t)blk * NPIX);
    const float4* gp = (const float4*)gk;

    const float4 v0 = xp[rm * 8 + q];          // row rb-1 (clamped)
    const float4 v1 = xp[rb * 8 + q];          // row rb
    const float4 v2 = xp[(rb + 1) * 8 + q];    // row rb+1
    const float4 v3 = xp[rp * 8 + q];          // row rb+2 (clamped)
    const float4 g0 = gp[rb * 8 + q];
    const float4 g1 = gp[(rb + 1) * 8 + q];

    float* hcol = hist + tid;                  // scatter base: addr = base + bin*512
    __syncthreads();   // hist zeroed by all threads

    // ---- process 2 rows x 4 cols (bin/weight chain bit-identical to R5/R14) ----
    #pragma unroll
    for (int i = 0; i < 2; i++) {
        const float4 up = (i == 0) ? v0 : v1;
        const float4 ce = (i == 0) ? v1 : v2;
        const float4 dn = (i == 0) ? v2 : v3;
        const float4 gg = (i == 0) ? g0 : g1;

        // horizontal neighbors across quad edges (replicate-pad at patch edges)
        float lt = __shfl_up_sync(0xffffffffu, ce.w, 1);
        float rt = __shfl_down_sync(0xffffffffu, ce.x, 1);
        if (q == 0) lt = ce.x;
        if (q == 7) rt = ce.w;

        const float cl[4] = { lt,   ce.x, ce.y, ce.z };
        const float cc[4] = { ce.x, ce.y, ce.z, ce.w };
        const float cr[4] = { ce.y, ce.z, ce.w, rt   };
        const float cu[4] = { up.x, up.y, up.z, up.w };
        const float cd[4] = { dn.x, dn.y, dn.z, dn.w };
        const float cg[4] = { gg.x, gg.y, gg.z, gg.w };

        #pragma unroll
        for (int j = 0; j < 4; j++) {
            const float gxv = gw0 * (cl[j] - cr[j]);   // == gw0*cl + 0*cc + (-gw0)*cr, bit-exact
            const float gyv = hw0 * (cu[j] - cd[j]);
            const float mag = sqrt_approx(gxv * gxv + gyv * gyv + 1e-10f) * cg[j];

            if (mag > 0.001f) {
                const float ori = atan2f(gyv, gxv);
                // jnp.mod(ori, 2pi): floor in {-1,0} -> bitwise-equal select
                const float m    = (ori < 0.0f) ? ori + TWO_PI_F : ori;
                const float xnum = 36.0f * m;
                // Markstein constant division: ob = xnum / 2pi, correctly rounded
                const float qd = xnum * INV_2PI;
                const float rr = fmaf(-TWO_PI_F, qd, xnum);
                const float ob = fmaf(rr, INV_2PI, qd);

                const float bf = floorf(ob);
                const float w  = (1.0f - (ob - bf)) * mag;     // wo0
                int bin = (int)bf;
                if (bin >= NBINS) bin = 0;                     // ob==36 edge -> mod
                hcol[bin * THREADS] += w;                      // bank = lane, conflict-free
            }
        }
    }
    __syncthreads();

    // ---- reduction: fold 128->32 + butterfly; UNROLLED so the 9 SHFL chains
    //      are independent and latency-overlapped (the R12/R13 defect fixed) ----
    #pragma unroll
    for (int k = 0; k < 9; k++) {
        const int b = wrp + 4 * k;                 // warp w owns bins w, w+4, ...
        const float* col = hist + b * THREADS;
        float s = (col[lane] + col[lane + 32]) + (col[lane + 64] + col[lane + 96]);
        s += __shfl_xor_sync(0xffffffffu, s, 16);
        s += __shfl_xor_sync(0xffffffffu, s, 8);
        s += __shfl_xor_sync(0xffffffffu, s, 4);
        s += __shfl_xor_sync(0xffffffffu, s, 2);
        s += __shfl_xor_sync(0xffffffffu, s, 1);
        if (lane == 0) hred[b] = s * (1.0f / (float)NPIX);
    }
    __syncthreads();

    // ---- smoothing in parallel (36 threads), then tid0 pure max scan ----
    if (tid < NBINS) {
        const float w0 = smw[0], w1 = smw[1], w2 = smw[2];
        const float l  = (tid > 0)         ? hred[tid - 1] : 0.0f;
        const float r  = (tid < NBINS - 1) ? hred[tid + 1] : 0.0f;
        smarr[tid] = w0 * l + w1 * hred[tid] + w2 * r;
    }
    __syncthreads();

    if (tid == 0) {
        float best = -INFINITY;
        int   bi   = 0;
        #pragma unroll
        for (int k = 0; k < NBINS; k++) {
            const float sm = smarr[k];
            if (sm > best) { best = sm; bi = k; }   // strict > : first occurrence
        }
        out[blk] = -((TWO_PI_F * (float)bi) / (float)NBINS - PI_F);
    }
}

extern "C" void kernel_launch(void* const* d_in, const int* in_sizes, int n_in,
                              void* d_out, int out_size)
{
    const float* x   = (const float*)d_in[0];   // [B,1,32,32]
    const float* gxw = (const float*)d_in[1];   // [3]
    const float* gyw = (const float*)d_in[2];   // [3]
    const float* smw = (const float*)d_in[3];   // [3]
    const float* gk  = (const float*)d_in[4];   // [32,32]
    float* out = (float*)d_out;                 // [B]

    const int B = in_sizes[0] / NPIX;
    orientation_kernel<<<B, THREADS>>>(x, gxw, gyw, smw, gk, out);
}

// round 16
// speedup vs baseline: 1.1043x; 1.1043x over previous
#include <cuda_runtime.h>
#include <math.h>

#define PS      32
#define NPIX    1024
#define NBINS   36
#define THREADS 128
#define HSTRIDE 37   // 36 bins + pad; 37 mod 32 = 5 (coprime) -> bank permutation per row

__device__ __forceinline__ float sqrt_approx(float v) {
    float r;
    asm("sqrt.approx.f32 %0, %1;" : "=f"(r) : "f"(v));
    return r;
}

__global__ __launch_bounds__(THREADS, 8)
void orientation_kernel(const float* __restrict__ x,
                        const float* __restrict__ gxw,
                        const float* __restrict__ gyw,
                        const float* __restrict__ smw,
                        const float* __restrict__ gk,
                        float* __restrict__ out)
{
    __shared__ float hist[THREADS * HSTRIDE];   // per-thread private histograms
    __shared__ float hred[NBINS];
    __shared__ float smarr[NBINS];

    const int tid  = threadIdx.x;
    const int lane = tid & 31;
    const int wrp  = tid >> 5;
    const int q    = lane & 7;          // col-quad: cols 4q..4q+3
    const int rg   = lane >> 3;         // rowgroup within warp
    const int blk  = blockIdx.x;

    const float TWO_PI_F = __int_as_float(0x40C90FDB);   // RN(2*pi)
    const float INV_2PI  = __int_as_float(0x3E22F983);   // RN(1/(2*pi))
    const float PI_F     = 3.141592653589793f;

    // ---- zero histogram block-cooperatively with STS.128 ----
    {
        float4 z = make_float4(0.f, 0.f, 0.f, 0.f);
        float4* h4 = (float4*)hist;
        #pragma unroll
        for (int i = 0; i < (THREADS * HSTRIDE + 3) / 4; i += THREADS) {
            int idx = i + tid;
            if (idx < (THREADS * HSTRIDE) / 4) h4[idx] = z;
        }
    }

    // gx_w = [0.5, 0, -0.5]: middle tap contributes exactly +0 and gw2 = -gw0,
    // so RN(gw0*a + 0) + RN(-gw0*b) == gw0 * RN(a-b)  (gw0 = 2^-1, a power of
    // two, commutes with RN). Bit-exact vs the reference chain. Same for gy_w.
    const float gw0 = gxw[0];
    const float hw0 = gyw[0];

    // ---- vectorized loads: thread owns rows rb,rb+1 x cols 4q..4q+3 ----
    const int g  = wrp * 4 + rg;        // global rowgroup 0..15
    const int rb = 2 * g;               // base row (even)
    const int rm = (rb - 1 < 0) ? 0 : rb - 1;
    const int rp = (rb + 2 > PS - 1) ? PS - 1 : rb + 2;

    const float4* xp = (const float4*)(x + (size_t)blk * NPIX);
    const float4* gp = (const float4*)gk;

    const float4 v0 = xp[rm * 8 + q];          // row rb-1 (clamped)
    const float4 v1 = xp[rb * 8 + q];          // row rb
    const float4 v2 = xp[(rb + 1) * 8 + q];    // row rb+1
    const float4 v3 = xp[rp * 8 + q];          // row rb+2 (clamped)
    const float4 g0 = gp[rb * 8 + q];
    const float4 g1 = gp[(rb + 1) * 8 + q];

    float* hrow = hist + tid * HSTRIDE;
    __syncthreads();   // hist zeroed by all threads

    // ---- process 2 rows x 4 cols (bin chain bit-identical to R5/R14) ----
    #pragma unroll
    for (int i = 0; i < 2; i++) {
        const float4 up = (i == 0) ? v0 : v1;
        const float4 ce = (i == 0) ? v1 : v2;
        const float4 dn = (i == 0) ? v2 : v3;
        const float4 gg = (i == 0) ? g0 : g1;

        // horizontal neighbors across quad edges (replicate-pad at patch edges)
        float lt = __shfl_up_sync(0xffffffffu, ce.w, 1);
        float rt = __shfl_down_sync(0xffffffffu, ce.x, 1);
        if (q == 0) lt = ce.x;
        if (q == 7) rt = ce.w;

        const float cl[4] = { lt,   ce.x, ce.y, ce.z };
        const float cr[4] = { ce.y, ce.z, ce.w, rt   };
        const float cu[4] = { up.x, up.y, up.z, up.w };
        const float cd[4] = { dn.x, dn.y, dn.z, dn.w };
        const float cg[4] = { gg.x, gg.y, gg.z, gg.w };

        #pragma unroll
        for (int j = 0; j < 4; j++) {
            const float gxv = gw0 * (cl[j] - cr[j]);   // bit-exact identity
            const float gyv = hw0 * (cu[j] - cd[j]);
            const float mag = sqrt_approx(gxv * gxv + gyv * gyv + 1e-10f) * cg[j];

            if (mag > 0.001f) {
                const float ori = atan2f(gyv, gxv);
                // jnp.mod(ori, 2pi): floor in {-1,0} -> bitwise-equal select
                const float m    = (ori < 0.0f) ? ori + TWO_PI_F : ori;
                const float xnum = 36.0f * m;
                // Markstein constant division: ob = xnum / 2pi, correctly rounded
                const float qd = xnum * INV_2PI;
                const float rr = fmaf(-TWO_PI_F, qd, xnum);
                const float ob = fmaf(rr, INV_2PI, qd);

                const float bf = floorf(ob);
                // (1 - (ob-bf))*mag as one FMA; ob-bf is exact, so this is a
                // <=1-ulp random perturbation of w (same safe channel as
                // sqrt_approx on mag).
                const float w  = fmaf(bf - ob, mag, mag);
                int bin = (int)bf;
                if (bin >= NBINS) bin = 0;                     // ob==36 edge -> mod
                hrow[bin] += w;
            }
        }
    }
    __syncthreads();

    // ---- reduce 128 private rows -> 36 bins (R14 form; bank=(5r+lane) ok) ----
    if (tid < NBINS) {
        float s0 = 0.f, s1 = 0.f, s2 = 0.f, s3 = 0.f;
        #pragma unroll
        for (int r = 0; r < THREADS; r += 4) {
            s0 += hist[(r + 0) * HSTRIDE + tid];
            s1 += hist[(r + 1) * HSTRIDE + tid];
            s2 += hist[(r + 2) * HSTRIDE + tid];
            s3 += hist[(r + 3) * HSTRIDE + tid];
        }
        hred[tid] = ((s0 + s1) + (s2 + s3)) * (1.0f / (float)NPIX);
    }
    __syncthreads();

    // ---- smoothing in parallel (36 threads), then tid0 pure max scan ----
    if (tid < NBINS) {
        const float w0 = smw[0], w1 = smw[1], w2 = smw[2];
        const float l  = (tid > 0)         ? hred[tid - 1] : 0.0f;
        const float r  = (tid < NBINS - 1) ? hred[tid + 1] : 0.0f;
        smarr[tid] = w0 * l + w1 * hred[tid] + w2 * r;
    }
    __syncthreads();

    if (tid == 0) {
        float best = -INFINITY;
        int   bi   = 0;
        #pragma unroll
        for (int k = 0; k < NBINS; k++) {
            const float sm = smarr[k];
            if (sm > best) { best = sm; bi = k; }   // strict > : first occurrence
        }
        out[blk] = -((TWO_PI_F * (float)bi) / (float)NBINS - PI_F);
    }
}

extern "C" void kernel_launch(void* const* d_in, const int* in_sizes, int n_in,
                              void* d_out, int out_size)
{
    const float* x   = (const float*)d_in[0];   // [B,1,32,32]
    const float* gxw = (const float*)d_in[1];   // [3]
    const float* gyw = (const float*)d_in[2];   // [3]
    const float* smw = (const float*)d_in[3];   // [3]
    const float* gk  = (const float*)d_in[4];   // [32,32]
    float* out = (float*)d_out;                 // [B]

    const int B = in_sizes[0] / NPIX;
    orientation_kernel<<<B, THREADS>>>(x, gxw, gyw, smw, gk, out);
}